// round 16
// baseline (speedup 1.0000x reference)
#include <cuda_runtime.h>
#include <cuda_fp16.h>
#include <cstdint>

// Problem constants
#define Bb 4
#define Tt 8192
#define Hh 1024
#define Rr 1024
#define N1 2048          // 2*R
#define NSEG 64
#define SEGLEN 128       // Tt / NSEG

// ---------------- scratch (static device globals; no allocation) ----------------
__device__ __half g_x1[(size_t)Bb * Tt * Hh];       // conv output (fp16)
__device__ __half g_zh[(size_t)Bb * Tt * N1];       // GEMM1 out: (a,b) half pairs
__device__ __half g_ho[(size_t)Bb * Tt * Rr];       // scan output (fp16)
__device__ float  g_segA[(size_t)Bb * NSEG * Rr];
__device__ float  g_segC[(size_t)Bb * NSEG * Rr];
__device__ float  g_hin [(size_t)Bb * NSEG * Rr];
__device__ __half g_wzhT [(size_t)N1 * Hh];         // w_zh fp16, row-interleaved (z,h)
__device__ __half g_woutT[(size_t)Hh * Rr];         // w_out fp16

// ================= helpers =================
__device__ __forceinline__ uint32_t smem_to_u32(const void* p) {
    uint32_t a;
    asm("{ .reg .u64 t; cvta.to.shared.u64 t, %1; cvt.u32.u64 %0, t; }" : "=r"(a) : "l"(p));
    return a;
}
__device__ __forceinline__ void cp_async16(uint32_t dst, const void* src) {
    asm volatile("cp.async.cg.shared.global [%0], [%1], 16;" :: "r"(dst), "l"(src) : "memory");
}
#define CP_COMMIT() asm volatile("cp.async.commit_group;" ::: "memory")
#define CP_WAIT(n)  asm volatile("cp.async.wait_group %0;" :: "n"(n) : "memory")

__device__ __forceinline__ void mma_f16(float* c, const uint32_t* a, const uint32_t* b) {
    asm volatile(
        "mma.sync.aligned.m16n8k16.row.col.f32.f16.f16.f32 "
        "{%0,%1,%2,%3}, {%4,%5,%6,%7}, {%8,%9}, {%0,%1,%2,%3};"
        : "+f"(c[0]), "+f"(c[1]), "+f"(c[2]), "+f"(c[3])
        : "r"(a[0]), "r"(a[1]), "r"(a[2]), "r"(a[3]), "r"(b[0]), "r"(b[1]));
}
__device__ __forceinline__ void ldmatrix_x4(uint32_t* r, uint32_t addr) {
    asm volatile("ldmatrix.sync.aligned.m8n8.x4.shared.b16 {%0,%1,%2,%3}, [%4];"
        : "=r"(r[0]), "=r"(r[1]), "=r"(r[2]), "=r"(r[3]) : "r"(addr));
}

// XOR-swizzled byte offset for tile element (row R, 16B-chunk ch) within a
// 128row x 32half operand tile packed as 64 physical 128B rows.
__device__ __forceinline__ uint32_t sw_addr(int R, int ch) {
    int p   = R >> 1;
    int lch = ch + ((R & 1) << 2);
    int pch = lch ^ (p & 7);
    return (uint32_t)(p * 128 + pch * 16);
}

// ================= weight prep (single launch, both weights) =================
// idx < N1*Hh        : w_zh -> g_wzhT with (z,h) row interleave
// idx >= N1*Hh       : w_out -> g_woutT plain
__global__ __launch_bounds__(256) void prep_weights_all(
    const float* __restrict__ w_zh, const float* __restrict__ w_out,
    __half* __restrict__ dzh, __half* __restrict__ dwo)
{
    int idx = blockIdx.x * blockDim.x + threadIdx.x;
    const int tw1 = N1 * Hh;
    if (idx < tw1) {
        int q = idx >> 10;
        int k = idx & 1023;
        int srow = (q & 1) ? (Rr + (q >> 1)) : (q >> 1);
        dzh[idx] = __float2half_rn(w_zh[(size_t)srow * Hh + k]);
    } else {
        int j = idx - tw1;
        if (j < Hh * Rr) dwo[j] = __float2half_rn(w_out[j]);
    }
}

// ================= fp16 mma.sync GEMM: C[M,N] = A[M,K] * B[N,K]^T =================
// 128x128x32 CTA tile, 8 warps (2x4), warp tile 64x32, 4-stage cp.async ring
// (3 in flight, WAIT(2)), XOR-swizzled smem (conflict-free stores + loads).
// B fragments of the whole stage preloaded; per mt: 2 A-ldmatrix -> 8 MMAs.
// FUSE=1: fused sigmoid/(a,b) epilogue + per-segment scan summaries.
#define BKH 32                       // halfs of K per stage
#define TILE_BYTES 8192              // 128 rows x 64B, swizzled
#define STG_BYTES  16384             // A + B
#define NST 4
#define GEMM_SMEM (128 * 64 * 8 + 2 * 128 * 8)   // 67584 (>= ring 65536)

template<int FUSE>
__global__ __launch_bounds__(256, 2)
void gemm_f16_mma(const __half* __restrict__ A, const __half* __restrict__ Bm,
                  void* __restrict__ Cv, int M, int N, int K)
{
    extern __shared__ __align__(128) char smraw[];
    uint32_t smem_base = smem_to_u32(smraw);

    int tid  = threadIdx.x;
    int wid  = tid >> 5;
    int lane = tid & 31;
    int bm = blockIdx.y * 128;
    int bn = blockIdx.x * 128;

    int warpM = (wid >> 2) * 64;   // 0 or 64
    int warpN = (wid & 3) * 32;    // 0..96

    int a_row = ((lane >> 3) & 1) * 8 + (lane & 7);
    int a_ch  = (lane >> 4);              // 16B chunk 0 or 1
    int b_row = (lane >> 4) * 8 + (lane & 7);
    int b_ch  = ((lane >> 3) & 1);

    // per-lane swizzled offsets (affine in mt/nt2: +1024B per 16 rows)
    uint32_t aoff[2], boff[2];
    aoff[0] = sw_addr(warpM + a_row, a_ch);
    aoff[1] = sw_addr(warpM + a_row, a_ch + 2);
    boff[0] = sw_addr(warpN + b_row, b_ch);
    boff[1] = sw_addr(warpN + b_row, b_ch + 2);

    int g = lane >> 2;
    int t = lane & 3;

    const int KT = K / BKH;

    float acc[4][4][4];
#pragma unroll
    for (int i = 0; i < 4; i++)
#pragma unroll
        for (int j = 0; j < 4; j++)
#pragma unroll
            for (int q = 0; q < 4; q++) acc[i][j][q] = 0.f;

    auto load_stage = [&](int kt, int s) {
        uint32_t aB = smem_base + s * STG_BYTES;
        uint32_t bB = aB + TILE_BYTES;
#pragma unroll
        for (int r = 0; r < 2; r++) {
            int c   = tid + 256 * r;       // 0..511
            int R   = c >> 2;
            int ch  = c & 3;
            uint32_t off = sw_addr(R, ch);
            cp_async16(aB + off, A + (size_t)(bm + R) * K + kt * BKH + ch * 8);
            cp_async16(bB + off, Bm + (size_t)(bn + R) * K + kt * BKH + ch * 8);
        }
        CP_COMMIT();
    };

    load_stage(0, 0);
    load_stage(1, 1);
    load_stage(2, 2);

    for (int kt = 0; kt < KT; kt++) {
        CP_WAIT(2);
        __syncthreads();

        int s = kt & (NST - 1);
        uint32_t aStage = smem_base + s * STG_BYTES;
        uint32_t bStage = aStage + TILE_BYTES;

        // preload ALL B fragments of this stage (both kc halves)
        uint32_t bfr[2][4][2];
#pragma unroll
        for (int kc = 0; kc < 2; kc++) {
#pragma unroll
            for (int nt2 = 0; nt2 < 2; nt2++) {
                uint32_t r[4];
                ldmatrix_x4(r, bStage + boff[kc] + nt2 * 1024);
                bfr[kc][2 * nt2][0]     = r[0];
                bfr[kc][2 * nt2][1]     = r[1];
                bfr[kc][2 * nt2 + 1][0] = r[2];
                bfr[kc][2 * nt2 + 1][1] = r[3];
            }
        }

        // per mt: 2 A-ldmatrix then 8 uninterrupted MMAs
#pragma unroll
        for (int mt = 0; mt < 4; mt++) {
            uint32_t afr0[4], afr1[4];
            ldmatrix_x4(afr0, aStage + aoff[0] + mt * 1024);
            ldmatrix_x4(afr1, aStage + aoff[1] + mt * 1024);
#pragma unroll
            for (int nt = 0; nt < 4; nt++)
                mma_f16(acc[mt][nt], afr0, bfr[0][nt]);
#pragma unroll
            for (int nt = 0; nt < 4; nt++)
                mma_f16(acc[mt][nt], afr1, bfr[1][nt]);
        }

        if (kt + 3 < KT) load_stage(kt + 3, (kt + 3) & (NST - 1));
        else             CP_COMMIT();
    }

    if (FUSE == 0) {
        float* C = (float*)Cv;
#pragma unroll
        for (int mt = 0; mt < 4; mt++) {
            int row = bm + warpM + mt * 16 + g;
#pragma unroll
            for (int nt = 0; nt < 4; nt++) {
                int col = bn + warpN + nt * 8 + t * 2;
                *(float2*)(C + (size_t)row * N + col) =
                    make_float2(acc[mt][nt][0], acc[mt][nt][1]);
                *(float2*)(C + (size_t)(row + 8) * N + col) =
                    make_float2(acc[mt][nt][2], acc[mt][nt][3]);
            }
        }
    } else {
        // fused epilogue: (z,h)->(a,b); half2 write + f32 stage; segment summary
        __half* C = (__half*)Cv;
        __syncthreads();
        float2* stg = (float2*)smraw;       // [row 0..127][channel 0..63], 64KB
#pragma unroll
        for (int mt = 0; mt < 4; mt++) {
            int rl = warpM + mt * 16 + g;
            int row = bm + rl;
#pragma unroll
            for (int nt = 0; nt < 4; nt++) {
                int ch  = (warpN >> 1) + nt * 4 + t;       // local channel 0..63
                int col = bn + warpN + nt * 8 + t * 2;     // half offset
                float s0 = 1.f / (1.f + __expf(-acc[mt][nt][0]));
                float a0 = 1.f - s0, b0 = s0 * acc[mt][nt][1];
                float s1 = 1.f / (1.f + __expf(-acc[mt][nt][2]));
                float a1 = 1.f - s1, b1 = s1 * acc[mt][nt][3];
                *(__half2*)(C + (size_t)row * N + col)       = __floats2half2_rn(a0, b0);
                *(__half2*)(C + (size_t)(row + 8) * N + col) = __floats2half2_rn(a1, b1);
                stg[rl * 64 + ch]       = make_float2(a0, b0);
                stg[(rl + 8) * 64 + ch] = make_float2(a1, b1);
            }
        }
        __syncthreads();
        float2* part = (float2*)(smraw + 128 * 64 * 8);    // 256 x float2
        {
            int ch = tid & 63;
            int q  = tid >> 6;                             // quarter 0..3
            float Aa = 1.f, Cc = 0.f;
#pragma unroll 8
            for (int i = q * 32; i < q * 32 + 32; i++) {
                float2 ab = stg[i * 64 + ch];
                Aa *= ab.x;
                Cc = ab.x * Cc + ab.y;
            }
            part[q * 64 + ch] = make_float2(Aa, Cc);
        }
        __syncthreads();
        if (tid < 64) {
            float Aa = 1.f, Cc = 0.f;
#pragma unroll
            for (int q = 0; q < 4; q++) {
                float2 p = part[q * 64 + tid];
                Cc = p.x * Cc + p.y;
                Aa *= p.x;
            }
            int b   = bm >> 13;                 // / Tt
            int seg = (bm & (Tt - 1)) >> 7;     // / SEGLEN
            int rglob = blockIdx.x * 64 + tid;
            size_t i = ((size_t)b * NSEG + seg) * Rr + rglob;
            g_segA[i] = Aa;
            g_segC[i] = Cc;
        }
    }
}

// ---------------- 1) residual causal depthwise conv (fp16 out, 8 ch/thread) ----
__global__ __launch_bounds__(256) void conv_residual(
    const float* __restrict__ x, const float* __restrict__ w,
    const float* __restrict__ cb)
{
    int idx = blockIdx.x * blockDim.x + threadIdx.x;    // over B*T*(H/8)
    int h8 = idx & 127;                                 // H/8 = 128
    int t  = (idx >> 7) & (Tt - 1);
    int b  = idx >> (7 + 13);
    size_t base = (((size_t)b * Tt + t) * Hh) + (size_t)h8 * 8;

    float4 xc0 = *(const float4*)(x + base);
    float4 xc1 = *(const float4*)(x + base + 4);
    float4 bc0 = *(const float4*)(cb + (size_t)h8 * 8);
    float4 bc1 = *(const float4*)(cb + (size_t)h8 * 8 + 4);
    float a0 = xc0.x + bc0.x, a1 = xc0.y + bc0.y, a2 = xc0.z + bc0.z, a3 = xc0.w + bc0.w;
    float a4 = xc1.x + bc1.x, a5 = xc1.y + bc1.y, a6 = xc1.z + bc1.z, a7 = xc1.w + bc1.w;

#pragma unroll
    for (int i = 0; i < 4; i++) {
        int ts = t - 3 + i;
        if (ts >= 0) {
            float4 xi0, xi1;
            if (i == 3) { xi0 = xc0; xi1 = xc1; }
            else {
                xi0 = *(const float4*)(x + base + (long long)(i - 3) * Hh);
                xi1 = *(const float4*)(x + base + (long long)(i - 3) * Hh + 4);
            }
            float4 wi0 = *(const float4*)(w + (size_t)i * Hh + (size_t)h8 * 8);
            float4 wi1 = *(const float4*)(w + (size_t)i * Hh + (size_t)h8 * 8 + 4);
            a0 += wi0.x * xi0.x; a1 += wi0.y * xi0.y;
            a2 += wi0.z * xi0.z; a3 += wi0.w * xi0.w;
            a4 += wi1.x * xi1.x; a5 += wi1.y * xi1.y;
            a6 += wi1.z * xi1.z; a7 += wi1.w * xi1.w;
        }
    }
    __half2 h01 = __floats2half2_rn(a0, a1);
    __half2 h23 = __floats2half2_rn(a2, a3);
    __half2 h45 = __floats2half2_rn(a4, a5);
    __half2 h67 = __floats2half2_rn(a6, a7);
    uint4 packed = make_uint4(*(uint32_t*)&h01, *(uint32_t*)&h23,
                              *(uint32_t*)&h45, *(uint32_t*)&h67);
    *(uint4*)(g_x1 + base) = packed;
}

// ---------------- 3) scan over segments ----------------
__global__ __launch_bounds__(128) void scan_passB()
{
    int r = blockIdx.x * 128 + threadIdx.x;
    int b = blockIdx.z;
    float h = 0.f;
    size_t base = (size_t)b * NSEG * Rr + r;
#pragma unroll 16
    for (int seg = 0; seg < NSEG; seg++) {
        size_t i = base + (size_t)seg * Rr;
        g_hin[i] = h;
        h = g_segA[i] * h + g_segC[i];
    }
}

// pass C: local scan with incoming prefix; 8 channels/thread, half (a,b) pairs
__global__ __launch_bounds__(128) void scan_passC()
{
    int ro  = blockIdx.x * 128 + threadIdx.x;   // octet index 0..127
    int seg = blockIdx.y;
    int b   = blockIdx.z;

    float4 hv0 = *(const float4*)(g_hin + ((size_t)b * NSEG + seg) * Rr + 8 * ro);
    float4 hv1 = *(const float4*)(g_hin + ((size_t)b * NSEG + seg) * Rr + 8 * ro + 4);
    float h0 = hv0.x, h1 = hv0.y, h2 = hv0.z, h3 = hv0.w;
    float h4 = hv1.x, h5 = hv1.y, h6 = hv1.z, h7 = hv1.w;
    int t0 = seg * SEGLEN;
#pragma unroll 4
    for (int t = t0; t < t0 + SEGLEN; t++) {
        const __half* src = g_zh + ((size_t)b * Tt + t) * N1 + 16 * ro;
        uint4 v0 = *(const uint4*)(src);
        uint4 v1 = *(const uint4*)(src + 8);
        float2 p0 = __half22float2(*(__half2*)&v0.x);
        float2 p1 = __half22float2(*(__half2*)&v0.y);
        float2 p2 = __half22float2(*(__half2*)&v0.z);
        float2 p3 = __half22float2(*(__half2*)&v0.w);
        float2 p4 = __half22float2(*(__half2*)&v1.x);
        float2 p5 = __half22float2(*(__half2*)&v1.y);
        float2 p6 = __half22float2(*(__half2*)&v1.z);
        float2 p7 = __half22float2(*(__half2*)&v1.w);
        h0 = p0.x * h0 + p0.y;
        h1 = p1.x * h1 + p1.y;
        h2 = p2.x * h2 + p2.y;
        h3 = p3.x * h3 + p3.y;
        h4 = p4.x * h4 + p4.y;
        h5 = p5.x * h5 + p5.y;
        h6 = p6.x * h6 + p6.y;
        h7 = p7.x * h7 + p7.y;
        __half2 o01 = __floats2half2_rn(h0, h1);
        __half2 o23 = __floats2half2_rn(h2, h3);
        __half2 o45 = __floats2half2_rn(h4, h5);
        __half2 o67 = __floats2half2_rn(h6, h7);
        *(uint4*)(g_ho + ((size_t)b * Tt + t) * Rr + 8 * ro) =
            make_uint4(*(uint32_t*)&o01, *(uint32_t*)&o23,
                       *(uint32_t*)&o45, *(uint32_t*)&o67);
    }
}

// ---------------- launch ----------------
extern "C" void kernel_launch(void* const* d_in, const int* in_sizes, int n_in,
                              void* d_out, int out_size)
{
    const float* x      = (const float*)d_in[0];
    const float* w_zh   = (const float*)d_in[1];
    const float* w_out  = (const float*)d_in[2];
    const float* conv_w = (const float*)d_in[3];
    const float* conv_b = (const float*)d_in[4];
    float* out = (float*)d_out;

    __half* x1 = nullptr; __half* zh = nullptr; __half* ho = nullptr;
    __half* wzhT = nullptr; __half* woutT = nullptr;
    cudaGetSymbolAddress((void**)&x1, g_x1);
    cudaGetSymbolAddress((void**)&zh, g_zh);
    cudaGetSymbolAddress((void**)&ho, g_ho);
    cudaGetSymbolAddress((void**)&wzhT, g_wzhT);
    cudaGetSymbolAddress((void**)&woutT, g_woutT);

    cudaFuncSetAttribute(gemm_f16_mma<0>,
                         cudaFuncAttributeMaxDynamicSharedMemorySize, GEMM_SMEM);
    cudaFuncSetAttribute(gemm_f16_mma<1>,
                         cudaFuncAttributeMaxDynamicSharedMemorySize, GEMM_SMEM);

    // 0) weight prep (one launch for both weights)
    {
        int total = N1 * Hh + Hh * Rr;
        prep_weights_all<<<(total + 255) / 256, 256>>>(w_zh, w_out, wzhT, woutT);
    }
    // 1) conv (8 channels per thread)
    {
        int total8 = Bb * Tt * (Hh / 8);
        conv_residual<<<total8 / 256, 256>>>(x, conv_w, conv_b);
    }
    // 2) GEMM1 (+ fused sigmoid/pairs + segment summaries)
    {
        dim3 grid(N1 / 128, (Bb * Tt) / 128);
        gemm_f16_mma<1><<<grid, 256, GEMM_SMEM>>>(x1, wzhT, zh, Bb * Tt, N1, Hh);
    }
    // 3) scan: segment prefix + local rescan
    {
        dim3 gB(Rr / 128, 1, Bb);
        scan_passB<<<gB, 128>>>();
        dim3 gC(Rr / 1024, NSEG, Bb);
        scan_passC<<<gC, 128>>>();
    }
    // 4) GEMM2: out[BT, H] = ho[BT, R] * w_out[H, R]^T
    {
        dim3 grid(Hh / 128, (Bb * Tt) / 128);
        gemm_f16_mma<0><<<grid, 256, GEMM_SMEM>>>(ho, woutT, out, Bb * Tt, Hh, Rr);
    }
}

// round 17
// speedup vs baseline: 1.0846x; 1.0846x over previous
#include <cuda_runtime.h>
#include <cuda_fp16.h>
#include <cstdint>

// Problem constants
#define Bb 4
#define Tt 8192
#define Hh 1024
#define Rr 1024
#define N1 2048          // 2*R
#define NSEG 64
#define SEGLEN 128       // Tt / NSEG

// ---------------- scratch (static device globals; no allocation) ----------------
__device__ __half g_x1[(size_t)Bb * Tt * Hh];       // conv output (fp16)
__device__ __half g_zh[(size_t)Bb * Tt * N1];       // GEMM1 out: (a,b) half pairs
__device__ __half g_ho[(size_t)Bb * Tt * Rr];       // scan output (fp16)
__device__ float  g_segA[(size_t)Bb * NSEG * Rr];
__device__ float  g_segC[(size_t)Bb * NSEG * Rr];
__device__ float  g_hin [(size_t)Bb * NSEG * Rr];
__device__ __half g_wzhT [(size_t)N1 * Hh];         // w_zh fp16, row-interleaved (z,h)
__device__ __half g_woutT[(size_t)Hh * Rr];         // w_out fp16

// ================= helpers =================
__device__ __forceinline__ uint32_t smem_to_u32(const void* p) {
    uint32_t a;
    asm("{ .reg .u64 t; cvta.to.shared.u64 t, %1; cvt.u32.u64 %0, t; }" : "=r"(a) : "l"(p));
    return a;
}
__device__ __forceinline__ void cp_async16(uint32_t dst, const void* src) {
    asm volatile("cp.async.cg.shared.global [%0], [%1], 16;" :: "r"(dst), "l"(src) : "memory");
}
#define CP_COMMIT() asm volatile("cp.async.commit_group;" ::: "memory")
#define CP_WAIT(n)  asm volatile("cp.async.wait_group %0;" :: "n"(n) : "memory")

__device__ __forceinline__ void mma_f16(float* c, const uint32_t* a, const uint32_t* b) {
    asm volatile(
        "mma.sync.aligned.m16n8k16.row.col.f32.f16.f16.f32 "
        "{%0,%1,%2,%3}, {%4,%5,%6,%7}, {%8,%9}, {%0,%1,%2,%3};"
        : "+f"(c[0]), "+f"(c[1]), "+f"(c[2]), "+f"(c[3])
        : "r"(a[0]), "r"(a[1]), "r"(a[2]), "r"(a[3]), "r"(b[0]), "r"(b[1]));
}
__device__ __forceinline__ void ldmatrix_x4(uint32_t* r, uint32_t addr) {
    asm volatile("ldmatrix.sync.aligned.m8n8.x4.shared.b16 {%0,%1,%2,%3}, [%4];"
        : "=r"(r[0]), "=r"(r[1]), "=r"(r[2]), "=r"(r[3]) : "r"(addr));
}

// XOR-swizzled byte offset for tile element (row R, 16B-chunk ch) within a
// 128row x 32half operand tile packed as 64 physical 128B rows.
__device__ __forceinline__ uint32_t sw_addr(int R, int ch) {
    int p   = R >> 1;
    int lch = ch + ((R & 1) << 2);
    int pch = lch ^ (p & 7);
    return (uint32_t)(p * 128 + pch * 16);
}

// ================= weight prep =================
__global__ __launch_bounds__(256) void prep_weight(
    const float* __restrict__ src, __half* __restrict__ dst, int total)
{
    int idx = blockIdx.x * blockDim.x + threadIdx.x;
    if (idx >= total) return;
    dst[idx] = __float2half_rn(src[idx]);
}
// w_zh: fp16 + row interleave (out row 2i = z-row i, out row 2i+1 = h-row i)
__global__ __launch_bounds__(256) void prep_weight_zh(
    const float* __restrict__ src, __half* __restrict__ dst)
{
    int idx = blockIdx.x * blockDim.x + threadIdx.x;   // over N1*Hh
    int q = idx >> 10;            // dst row
    int k = idx & 1023;
    int srow = (q & 1) ? (Rr + (q >> 1)) : (q >> 1);
    dst[idx] = __float2half_rn(src[(size_t)srow * Hh + k]);
}

// ================= fp16 mma.sync GEMM: C[M,N] = A[M,K] * B[N,K]^T =================
// 128x128x32 CTA tile, 8 warps (2x4), warp tile 64x32, 4-stage cp.async ring
// (3 in flight, WAIT(2)), XOR-swizzled smem (conflict-free stores + loads).
// B fragments of the whole stage preloaded; per mt: 2 A-ldmatrix -> 8 MMAs.
// FUSE=1: fused sigmoid/(a,b) epilogue + per-segment scan summaries.
#define BKH 32                       // halfs of K per stage
#define TILE_BYTES 8192              // 128 rows x 64B, swizzled
#define STG_BYTES  16384             // A + B
#define NST 4
#define GEMM_SMEM (128 * 64 * 8 + 2 * 128 * 8)   // 67584 (>= ring 65536)

template<int FUSE>
__global__ __launch_bounds__(256, 2)
void gemm_f16_mma(const __half* __restrict__ A, const __half* __restrict__ Bm,
                  void* __restrict__ Cv, int M, int N, int K)
{
    extern __shared__ __align__(128) char smraw[];
    uint32_t smem_base = smem_to_u32(smraw);

    int tid  = threadIdx.x;
    int wid  = tid >> 5;
    int lane = tid & 31;
    int bm = blockIdx.y * 128;
    int bn = blockIdx.x * 128;

    int warpM = (wid >> 2) * 64;   // 0 or 64
    int warpN = (wid & 3) * 32;    // 0..96

    int a_row = ((lane >> 3) & 1) * 8 + (lane & 7);
    int a_ch  = (lane >> 4);              // 16B chunk 0 or 1
    int b_row = (lane >> 4) * 8 + (lane & 7);
    int b_ch  = ((lane >> 3) & 1);

    // per-lane swizzled offsets (affine in mt/nt2: +1024B per 16 rows)
    uint32_t aoff[2], boff[2];
    aoff[0] = sw_addr(warpM + a_row, a_ch);
    aoff[1] = sw_addr(warpM + a_row, a_ch + 2);
    boff[0] = sw_addr(warpN + b_row, b_ch);
    boff[1] = sw_addr(warpN + b_row, b_ch + 2);

    int g = lane >> 2;
    int t = lane & 3;

    const int KT = K / BKH;

    float acc[4][4][4];
#pragma unroll
    for (int i = 0; i < 4; i++)
#pragma unroll
        for (int j = 0; j < 4; j++)
#pragma unroll
            for (int q = 0; q < 4; q++) acc[i][j][q] = 0.f;

    auto load_stage = [&](int kt, int s) {
        uint32_t aB = smem_base + s * STG_BYTES;
        uint32_t bB = aB + TILE_BYTES;
#pragma unroll
        for (int r = 0; r < 2; r++) {
            int c   = tid + 256 * r;       // 0..511
            int R   = c >> 2;
            int ch  = c & 3;
            uint32_t off = sw_addr(R, ch);
            cp_async16(aB + off, A + (size_t)(bm + R) * K + kt * BKH + ch * 8);
            cp_async16(bB + off, Bm + (size_t)(bn + R) * K + kt * BKH + ch * 8);
        }
        CP_COMMIT();
    };

    load_stage(0, 0);
    load_stage(1, 1);
    load_stage(2, 2);

    for (int kt = 0; kt < KT; kt++) {
        CP_WAIT(2);
        __syncthreads();

        int s = kt & (NST - 1);
        uint32_t aStage = smem_base + s * STG_BYTES;
        uint32_t bStage = aStage + TILE_BYTES;

        // preload ALL B fragments of this stage (both kc halves)
        uint32_t bfr[2][4][2];
#pragma unroll
        for (int kc = 0; kc < 2; kc++) {
#pragma unroll
            for (int nt2 = 0; nt2 < 2; nt2++) {
                uint32_t r[4];
                ldmatrix_x4(r, bStage + boff[kc] + nt2 * 1024);
                bfr[kc][2 * nt2][0]     = r[0];
                bfr[kc][2 * nt2][1]     = r[1];
                bfr[kc][2 * nt2 + 1][0] = r[2];
                bfr[kc][2 * nt2 + 1][1] = r[3];
            }
        }

        // per mt: 2 A-ldmatrix then 8 uninterrupted MMAs
#pragma unroll
        for (int mt = 0; mt < 4; mt++) {
            uint32_t afr0[4], afr1[4];
            ldmatrix_x4(afr0, aStage + aoff[0] + mt * 1024);
            ldmatrix_x4(afr1, aStage + aoff[1] + mt * 1024);
#pragma unroll
            for (int nt = 0; nt < 4; nt++)
                mma_f16(acc[mt][nt], afr0, bfr[0][nt]);
#pragma unroll
            for (int nt = 0; nt < 4; nt++)
                mma_f16(acc[mt][nt], afr1, bfr[1][nt]);
        }

        if (kt + 3 < KT) load_stage(kt + 3, (kt + 3) & (NST - 1));
        else             CP_COMMIT();
    }

    if (FUSE == 0) {
        float* C = (float*)Cv;
#pragma unroll
        for (int mt = 0; mt < 4; mt++) {
            int row = bm + warpM + mt * 16 + g;
#pragma unroll
            for (int nt = 0; nt < 4; nt++) {
                int col = bn + warpN + nt * 8 + t * 2;
                *(float2*)(C + (size_t)row * N + col) =
                    make_float2(acc[mt][nt][0], acc[mt][nt][1]);
                *(float2*)(C + (size_t)(row + 8) * N + col) =
                    make_float2(acc[mt][nt][2], acc[mt][nt][3]);
            }
        }
    } else {
        // fused epilogue: (z,h)->(a,b); half2 write + f32 stage; segment summary
        __half* C = (__half*)Cv;
        __syncthreads();
        float2* stg = (float2*)smraw;       // [row 0..127][channel 0..63], 64KB
#pragma unroll
        for (int mt = 0; mt < 4; mt++) {
            int rl = warpM + mt * 16 + g;
            int row = bm + rl;
#pragma unroll
            for (int nt = 0; nt < 4; nt++) {
                int ch  = (warpN >> 1) + nt * 4 + t;       // local channel 0..63
                int col = bn + warpN + nt * 8 + t * 2;     // half offset
                float s0 = 1.f / (1.f + __expf(-acc[mt][nt][0]));
                float a0 = 1.f - s0, b0 = s0 * acc[mt][nt][1];
                float s1 = 1.f / (1.f + __expf(-acc[mt][nt][2]));
                float a1 = 1.f - s1, b1 = s1 * acc[mt][nt][3];
                *(__half2*)(C + (size_t)row * N + col)       = __floats2half2_rn(a0, b0);
                *(__half2*)(C + (size_t)(row + 8) * N + col) = __floats2half2_rn(a1, b1);
                stg[rl * 64 + ch]       = make_float2(a0, b0);
                stg[(rl + 8) * 64 + ch] = make_float2(a1, b1);
            }
        }
        __syncthreads();
        float2* part = (float2*)(smraw + 128 * 64 * 8);    // 256 x float2
        {
            int ch = tid & 63;
            int q  = tid >> 6;                             // quarter 0..3
            float Aa = 1.f, Cc = 0.f;
#pragma unroll 8
            for (int i = q * 32; i < q * 32 + 32; i++) {
                float2 ab = stg[i * 64 + ch];
                Aa *= ab.x;
                Cc = ab.x * Cc + ab.y;
            }
            part[q * 64 + ch] = make_float2(Aa, Cc);
        }
        __syncthreads();
        if (tid < 64) {
            float Aa = 1.f, Cc = 0.f;
#pragma unroll
            for (int q = 0; q < 4; q++) {
                float2 p = part[q * 64 + tid];
                Cc = p.x * Cc + p.y;
                Aa *= p.x;
            }
            int b   = bm >> 13;                 // / Tt
            int seg = (bm & (Tt - 1)) >> 7;     // / SEGLEN
            int rglob = blockIdx.x * 64 + tid;
            size_t i = ((size_t)b * NSEG + seg) * Rr + rglob;
            g_segA[i] = Aa;
            g_segC[i] = Cc;
        }
    }
}

// ---------------- 1) residual causal depthwise conv (fp16 out) ----------------
__global__ __launch_bounds__(256) void conv_residual(
    const float* __restrict__ x, const float* __restrict__ w,
    const float* __restrict__ cb)
{
    int idx = blockIdx.x * blockDim.x + threadIdx.x;
    int h4 = idx & 255;
    int t  = (idx >> 8) & (Tt - 1);
    int b  = idx >> (8 + 13);
    size_t base = (((size_t)b * Tt + t) * Hh) + (size_t)h4 * 4;

    float4 xc = *(const float4*)(x + base);
    float4 bc = *(const float4*)(cb + (size_t)h4 * 4);
    float4 acc;
    acc.x = xc.x + bc.x; acc.y = xc.y + bc.y;
    acc.z = xc.z + bc.z; acc.w = xc.w + bc.w;

#pragma unroll
    for (int i = 0; i < 4; i++) {
        int ts = t - 3 + i;
        if (ts >= 0) {
            float4 xi = (i == 3) ? xc
                : *(const float4*)(x + base + (long long)(i - 3) * Hh);
            float4 wi = *(const float4*)(w + (size_t)i * Hh + (size_t)h4 * 4);
            acc.x += wi.x * xi.x; acc.y += wi.y * xi.y;
            acc.z += wi.z * xi.z; acc.w += wi.w * xi.w;
        }
    }
    __half2 h01 = __floats2half2_rn(acc.x, acc.y);
    __half2 h23 = __floats2half2_rn(acc.z, acc.w);
    uint2 packed = make_uint2(*(uint32_t*)&h01, *(uint32_t*)&h23);
    *(uint2*)(g_x1 + base) = packed;
}

// ---------------- 3) scan over segments (batched prefetch) ----------------
__global__ __launch_bounds__(128) void scan_passB()
{
    int r = blockIdx.x * 128 + threadIdx.x;
    int b = blockIdx.z;
    float h = 0.f;
    size_t base = (size_t)b * NSEG * Rr + r;
    // chunks of 8: batch the 16 independent loads, then run the dependent chain
    for (int c0 = 0; c0 < NSEG; c0 += 8) {
        float As[8], Cs[8];
#pragma unroll
        for (int j = 0; j < 8; j++) {
            size_t i = base + (size_t)(c0 + j) * Rr;
            As[j] = g_segA[i];
            Cs[j] = g_segC[i];
        }
#pragma unroll
        for (int j = 0; j < 8; j++) {
            g_hin[base + (size_t)(c0 + j) * Rr] = h;
            h = As[j] * h + Cs[j];
        }
    }
}

// pass C: local scan with incoming prefix; 4 channels/thread, half (a,b) pairs
__global__ __launch_bounds__(128) void scan_passC()
{
    int rq  = blockIdx.x * 128 + threadIdx.x;   // quad index 0..255
    int seg = blockIdx.y;
    int b   = blockIdx.z;

    float4 hv = *(const float4*)(g_hin + ((size_t)b * NSEG + seg) * Rr + 4 * rq);
    float h0 = hv.x, h1 = hv.y, h2 = hv.z, h3 = hv.w;
    int t0 = seg * SEGLEN;
#pragma unroll 4
    for (int t = t0; t < t0 + SEGLEN; t++) {
        uint4 v = *(const uint4*)(g_zh + ((size_t)b * Tt + t) * N1 + 8 * rq);
        float2 p0 = __half22float2(*(__half2*)&v.x);
        float2 p1 = __half22float2(*(__half2*)&v.y);
        float2 p2 = __half22float2(*(__half2*)&v.z);
        float2 p3 = __half22float2(*(__half2*)&v.w);
        h0 = p0.x * h0 + p0.y;
        h1 = p1.x * h1 + p1.y;
        h2 = p2.x * h2 + p2.y;
        h3 = p3.x * h3 + p3.y;
        __half2 o01 = __floats2half2_rn(h0, h1);
        __half2 o23 = __floats2half2_rn(h2, h3);
        *(uint2*)(g_ho + ((size_t)b * Tt + t) * Rr + 4 * rq) =
            make_uint2(*(uint32_t*)&o01, *(uint32_t*)&o23);
    }
}

// ---------------- launch ----------------
extern "C" void kernel_launch(void* const* d_in, const int* in_sizes, int n_in,
                              void* d_out, int out_size)
{
    const float* x      = (const float*)d_in[0];
    const float* w_zh   = (const float*)d_in[1];
    const float* w_out  = (const float*)d_in[2];
    const float* conv_w = (const float*)d_in[3];
    const float* conv_b = (const float*)d_in[4];
    float* out = (float*)d_out;

    __half* x1 = nullptr; __half* zh = nullptr; __half* ho = nullptr;
    __half* wzhT = nullptr; __half* woutT = nullptr;
    cudaGetSymbolAddress((void**)&x1, g_x1);
    cudaGetSymbolAddress((void**)&zh, g_zh);
    cudaGetSymbolAddress((void**)&ho, g_ho);
    cudaGetSymbolAddress((void**)&wzhT, g_wzhT);
    cudaGetSymbolAddress((void**)&woutT, g_woutT);

    cudaFuncSetAttribute(gemm_f16_mma<0>,
                         cudaFuncAttributeMaxDynamicSharedMemorySize, GEMM_SMEM);
    cudaFuncSetAttribute(gemm_f16_mma<1>,
                         cudaFuncAttributeMaxDynamicSharedMemorySize, GEMM_SMEM);

    // 0) weight prep
    {
        int tw1 = N1 * Hh;
        prep_weight_zh<<<(tw1 + 255) / 256, 256>>>(w_zh, wzhT);
        int tw2 = Hh * Rr;
        prep_weight<<<(tw2 + 255) / 256, 256>>>(w_out, woutT, tw2);
    }
    // 1) conv
    {
        int total4 = Bb * Tt * (Hh / 4);
        conv_residual<<<total4 / 256, 256>>>(x, conv_w, conv_b);
    }
    // 2) GEMM1 (+ fused sigmoid/pairs + segment summaries)
    {
        dim3 grid(N1 / 128, (Bb * Tt) / 128);
        gemm_f16_mma<1><<<grid, 256, GEMM_SMEM>>>(x1, wzhT, zh, Bb * Tt, N1, Hh);
    }
    // 3) scan: segment prefix + local rescan
    {
        dim3 gB(Rr / 128, 1, Bb);
        scan_passB<<<gB, 128>>>();
        dim3 gC(Rr / 512, NSEG, Bb);
        scan_passC<<<gC, 128>>>();
    }
    // 4) GEMM2: out[BT, H] = ho[BT, R] * w_out[H, R]^T
    {
        dim3 grid(Hh / 128, (Bb * Tt) / 128);
        gemm_f16_mma<0><<<grid, 256, GEMM_SMEM>>>(ho, woutT, out, Bb * Tt, Hh, Rr);
    }
}